// round 4
// baseline (speedup 1.0000x reference)
#include <cuda_runtime.h>
#include <math.h>

// Problem constants
#define KSZ    5
#define ICAPS  8
#define IA     32
#define NC     8
#define NA     32
#define HH     64
#define WW     64
#define BB     8
#define NIMG   64            // BB * ICAPS
#define COUT   256           // NC * NA
#define KVOL   (IA * KSZ * KSZ)   // 800
#define HW     (HH * WW)          // 4096

#define TILE    16
#define CCHUNK  16           // output channels per CTA

// 64 * 4096 * 256 floats = 256 MB scratch for votes, layout [n][h*w][cout]
__device__ float g_votes[(size_t)NIMG * HW * COUT];

// ---------------------------------------------------------------------------
// Conv kernel: direct 5x5 conv, fp32.
// CTA = (cout-chunk of 16, image n). Weights for the 16 couts loaded ONCE into
// SMEM (broadcast reads via LDS.128). CTA loops over 16 pixel tiles of 16x16,
// each with a 20x20 halo'd input tile in SMEM. Each thread owns 1 pixel x 16
// couts -> 16 FFMA per (cin,ky,kx) against 1 input LDS + 4 broadcast LDS.128.
// ---------------------------------------------------------------------------
__global__ __launch_bounds__(256) void conv_votes_kernel(
    const float* __restrict__ x,   // [NIMG][IA][HH][WW]
    const float* __restrict__ Wt)  // [COUT][IA][5][5]
{
    extern __shared__ float smem[];
    float* sW  = smem;                 // [KVOL][CCHUNK] = 12800 floats
    float* sIn = smem + KVOL * CCHUNK; // [IA][20][20]   = 12800 floats

    const int tid   = threadIdx.x;
    const int chunk = blockIdx.x;      // 0..15
    const int n     = blockIdx.y;      // 0..63
    const int c0    = chunk * CCHUNK;

    // Load weight chunk: sW[k*16 + c] = W[(c0+c)*800 + k]
    // (coalesced on global: consecutive k for fixed c)
    for (int i = tid; i < KVOL * CCHUNK; i += 256) {
        int c = i / KVOL;
        int k = i - c * KVOL;
        sW[k * CCHUNK + c] = Wt[(c0 + c) * KVOL + k];
    }

    const float* xn = x + (size_t)n * IA * HW;
    const int py = tid >> 4;   // 0..15
    const int px = tid & 15;   // 0..15

    for (int tile = 0; tile < 16; ++tile) {
        const int th = (tile >> 2) * TILE;
        const int tw = (tile & 3) * TILE;

        __syncthreads();  // previous tile compute done (and, on iter 0, sW loaded... covered below)
        // Load input tile with halo: sIn[ca*400 + r*20 + cc], r,cc in [0,20)
        for (int i = tid; i < IA * 400; i += 256) {
            int ca = i / 400;
            int rem = i - ca * 400;
            int r  = rem / 20;
            int cc = rem - r * 20;
            int gh = th + r - 2;
            int gw = tw + cc - 2;
            float v = 0.0f;
            if ((unsigned)gh < (unsigned)HH && (unsigned)gw < (unsigned)WW)
                v = xn[ca * HW + gh * WW + gw];
            sIn[i] = v;
        }
        __syncthreads();

        float acc[CCHUNK];
#pragma unroll
        for (int c = 0; c < CCHUNK; ++c) acc[c] = 0.0f;

        const float* sI0 = &sIn[py * 20 + px];

#pragma unroll 1
        for (int ca = 0; ca < IA; ++ca) {
            const float*  sIc = sI0 + ca * 400;
            const float4* sWc = (const float4*)&sW[ca * 25 * CCHUNK];
#pragma unroll
            for (int ky = 0; ky < 5; ++ky) {
#pragma unroll
                for (int kx = 0; kx < 5; ++kx) {
                    const float xv = sIc[ky * 20 + kx];
                    const int kk = (ky * 5 + kx) * (CCHUNK / 4);
#pragma unroll
                    for (int q = 0; q < CCHUNK / 4; ++q) {
                        float4 w4 = sWc[kk + q];
                        acc[q * 4 + 0] += xv * w4.x;
                        acc[q * 4 + 1] += xv * w4.y;
                        acc[q * 4 + 2] += xv * w4.z;
                        acc[q * 4 + 3] += xv * w4.w;
                    }
                }
            }
        }

        // Write votes: [n][pix][cout], 64B contiguous per thread
        float* vp = &g_votes[((size_t)n * HW + (size_t)(th + py) * WW + (tw + px)) * COUT + c0];
#pragma unroll
        for (int q = 0; q < CCHUNK / 4; ++q) {
            float4 v4 = make_float4(acc[q * 4 + 0], acc[q * 4 + 1],
                                    acc[q * 4 + 2], acc[q * 4 + 3]);
            *(float4*)&vp[q * 4] = v4;
        }
    }
}

// ---------------------------------------------------------------------------
// Routing kernel: CTA = 8 consecutive pixels (same b, same h row), 8 warps,
// warp <-> pixel, lane <-> atom. Votes tile (8 pix x 8 ic x 256) staged once
// in SMEM; 3 routing iterations read only SMEM. Output written coalesced-ish
// via an activation staging buffer.
// ---------------------------------------------------------------------------
__global__ __launch_bounds__(256) void routing_kernel(
    const float* __restrict__ bias,   // [NC][NA]
    float* __restrict__ out)          // [BB][NC][NA][HH][WW]
{
    extern __shared__ float smem[];
    float* sv   = smem;            // [8][ICAPS][COUT]  16384 floats
    float* slog = sv + 8 * ICAPS * COUT;   // [8][ICAPS][NC]  512
    float* srt  = slog + 8 * ICAPS * NC;   // [8][ICAPS][NC]  512
    float* sact = srt + 8 * ICAPS * NC;    // [8][COUT]       2048

    const int tid  = threadIdx.x;
    const int warp = tid >> 5;   // local pixel 0..7
    const int lane = tid & 31;   // atom

    const int cta = blockIdx.x;       // b(8) * h(64) * wgroup(8)
    const int b   = cta >> 9;
    const int h   = (cta >> 3) & 63;
    const int wg  = cta & 7;
    const int pixbase = h * WW + wg * 8;

    // Stage votes: sv[p][ic][cout] <- g_votes[(b*8+ic)][pixbase+p][cout]
    for (int i = tid; i < 8 * ICAPS * COUT; i += 256) {
        int p    = i >> 11;          // /2048
        int ic   = (i >> 8) & 7;
        int cout = i & 255;
        sv[i] = g_votes[(((size_t)(b * ICAPS + ic)) * HW + pixbase + p) * COUT + cout];
    }
    // Zero logits
    for (int i = tid; i < 8 * ICAPS * NC; i += 256) slog[i] = 0.0f;

    // Per-lane bias: bias[nc][lane]
    float bv[NC];
#pragma unroll
    for (int nc = 0; nc < NC; ++nc) bv[nc] = bias[nc * NA + lane];

    __syncthreads();

    const float* svp = &sv[warp * ICAPS * COUT];
    float* slogp = &slog[warp * ICAPS * NC];
    float* srtp  = &srt[warp * ICAPS * NC];

    float p_[NC];
    float a_[NC];

#pragma unroll 1
    for (int it = 0; it < 3; ++it) {
        // Softmax over nc, lanes 0..7 each handle one ic
        if (lane < ICAPS) {
            const int ic = lane;
            float l[NC];
            float mx = -1e30f;
#pragma unroll
            for (int nc = 0; nc < NC; ++nc) {
                l[nc] = slogp[ic * NC + nc];
                mx = fmaxf(mx, l[nc]);
            }
            float s = 0.0f;
#pragma unroll
            for (int nc = 0; nc < NC; ++nc) {
                l[nc] = __expf(l[nc] - mx);
                s += l[nc];
            }
            float inv = 1.0f / s;
#pragma unroll
            for (int nc = 0; nc < NC; ++nc) srtp[ic * NC + nc] = l[nc] * inv;
        }
        __syncwarp();

        // preactivate: p[nc] = bias + sum_ic route[ic][nc] * v[ic][nc][lane]
#pragma unroll
        for (int nc = 0; nc < NC; ++nc) p_[nc] = bv[nc];
#pragma unroll
        for (int ic = 0; ic < ICAPS; ++ic) {
#pragma unroll
            for (int nc = 0; nc < NC; ++nc) {
                p_[nc] += srtp[ic * NC + nc] * svp[ic * COUT + nc * NA + lane];
            }
        }

        // squash: a = p * norm/(1+norm^2), norm over atoms (warp reduce)
#pragma unroll
        for (int nc = 0; nc < NC; ++nc) {
            float s = p_[nc] * p_[nc];
#pragma unroll
            for (int o = 16; o > 0; o >>= 1) s += __shfl_xor_sync(0xFFFFFFFFu, s, o);
            float scale = sqrtf(s) / (1.0f + s);
            a_[nc] = p_[nc] * scale;
        }

        if (it < 2) {
            // distances: d[ic][nc] = sum_atoms v * a ; logits += d
#pragma unroll
            for (int ic = 0; ic < ICAPS; ++ic) {
#pragma unroll
                for (int nc = 0; nc < NC; ++nc) {
                    float d = svp[ic * COUT + nc * NA + lane] * a_[nc];
#pragma unroll
                    for (int o = 16; o > 0; o >>= 1) d += __shfl_xor_sync(0xFFFFFFFFu, d, o);
                    if (lane == 0) slogp[ic * NC + nc] += d;
                }
            }
            __syncwarp();
        }
    }

    // Stage activation, then write out coalesced by (nc,na)
#pragma unroll
    for (int nc = 0; nc < NC; ++nc) sact[warp * COUT + nc * NA + lane] = a_[nc];
    __syncthreads();

    const int cout = tid;  // nc*32+na
    float* op = out + ((size_t)b * COUT + cout) * HW + pixbase;
#pragma unroll
    for (int p = 0; p < 8; ++p) op[p] = sact[p * COUT + cout];
}

// ---------------------------------------------------------------------------
extern "C" void kernel_launch(void* const* d_in, const int* in_sizes, int n_in,
                              void* d_out, int out_size)
{
    const float* x    = (const float*)d_in[0];  // [8,8,32,64,64]
    const float* Wt   = (const float*)d_in[1];  // [256,32,5,5]
    const float* bias = (const float*)d_in[2];  // [1,1,8,32]
    float* out = (float*)d_out;                 // [8,8,32,64,64]

    const int conv_smem = (KVOL * CCHUNK + IA * 400) * (int)sizeof(float);       // 102400 B
    const int rout_smem = (8 * ICAPS * COUT + 2 * 8 * ICAPS * NC + 8 * COUT)
                          * (int)sizeof(float);                                   // 77824 B

    cudaFuncSetAttribute(conv_votes_kernel,
                         cudaFuncAttributeMaxDynamicSharedMemorySize, conv_smem);
    cudaFuncSetAttribute(routing_kernel,
                         cudaFuncAttributeMaxDynamicSharedMemorySize, rout_smem);

    conv_votes_kernel<<<dim3(16, 64), 256, conv_smem>>>(x, Wt);
    routing_kernel<<<BB * HH * (WW / 8), 256, rout_smem>>>(bias, out);
}

// round 5
// speedup vs baseline: 1.0009x; 1.0009x over previous
#include <cuda_runtime.h>
#include <math.h>

// Problem constants
#define KSZ    5
#define ICAPS  8
#define IA     32
#define NC     8
#define NA     32
#define HH     64
#define WW     64
#define BB     8
#define NIMG   64            // BB * ICAPS
#define COUT   256           // NC * NA
#define KVOL   (IA * KSZ * KSZ)   // 800
#define HW     (HH * WW)          // 4096

#define TILE    16
#define CCHUNK  16           // output channels per CTA

// 64 * 4096 * 256 floats = 256 MB scratch for votes, layout [n][h*w][cout]
__device__ float g_votes[(size_t)NIMG * HW * COUT];

// ---------------------------------------------------------------------------
// Conv kernel: direct 5x5 conv, fp32.
// CTA = (cout-chunk of 16, image n). Weights for the 16 couts loaded ONCE into
// SMEM (broadcast reads via LDS.128). CTA loops over 16 pixel tiles of 16x16,
// each with a 20x20 halo'd input tile in SMEM. Each thread owns 1 pixel x 16
// couts -> 16 FFMA per (cin,ky,kx) against 1 input LDS + 4 broadcast LDS.128.
// ---------------------------------------------------------------------------
__global__ __launch_bounds__(256) void conv_votes_kernel(
    const float* __restrict__ x,   // [NIMG][IA][HH][WW]
    const float* __restrict__ Wt)  // [COUT][IA][5][5]
{
    extern __shared__ float smem[];
    float* sW  = smem;                 // [KVOL][CCHUNK] = 12800 floats
    float* sIn = smem + KVOL * CCHUNK; // [IA][20][20]   = 12800 floats

    const int tid   = threadIdx.x;
    const int chunk = blockIdx.x;      // 0..15
    const int n     = blockIdx.y;      // 0..63
    const int c0    = chunk * CCHUNK;

    // Load weight chunk: sW[k*16 + c] = W[(c0+c)*800 + k]
    // (coalesced on global: consecutive k for fixed c)
    for (int i = tid; i < KVOL * CCHUNK; i += 256) {
        int c = i / KVOL;
        int k = i - c * KVOL;
        sW[k * CCHUNK + c] = Wt[(c0 + c) * KVOL + k];
    }

    const float* xn = x + (size_t)n * IA * HW;
    const int py = tid >> 4;   // 0..15
    const int px = tid & 15;   // 0..15

    for (int tile = 0; tile < 16; ++tile) {
        const int th = (tile >> 2) * TILE;
        const int tw = (tile & 3) * TILE;

        __syncthreads();  // previous tile compute done (and, on iter 0, sW loaded... covered below)
        // Load input tile with halo: sIn[ca*400 + r*20 + cc], r,cc in [0,20)
        for (int i = tid; i < IA * 400; i += 256) {
            int ca = i / 400;
            int rem = i - ca * 400;
            int r  = rem / 20;
            int cc = rem - r * 20;
            int gh = th + r - 2;
            int gw = tw + cc - 2;
            float v = 0.0f;
            if ((unsigned)gh < (unsigned)HH && (unsigned)gw < (unsigned)WW)
                v = xn[ca * HW + gh * WW + gw];
            sIn[i] = v;
        }
        __syncthreads();

        float acc[CCHUNK];
#pragma unroll
        for (int c = 0; c < CCHUNK; ++c) acc[c] = 0.0f;

        const float* sI0 = &sIn[py * 20 + px];

#pragma unroll 1
        for (int ca = 0; ca < IA; ++ca) {
            const float*  sIc = sI0 + ca * 400;
            const float4* sWc = (const float4*)&sW[ca * 25 * CCHUNK];
#pragma unroll
            for (int ky = 0; ky < 5; ++ky) {
#pragma unroll
                for (int kx = 0; kx < 5; ++kx) {
                    const float xv = sIc[ky * 20 + kx];
                    const int kk = (ky * 5 + kx) * (CCHUNK / 4);
#pragma unroll
                    for (int q = 0; q < CCHUNK / 4; ++q) {
                        float4 w4 = sWc[kk + q];
                        acc[q * 4 + 0] += xv * w4.x;
                        acc[q * 4 + 1] += xv * w4.y;
                        acc[q * 4 + 2] += xv * w4.z;
                        acc[q * 4 + 3] += xv * w4.w;
                    }
                }
            }
        }

        // Write votes: [n][pix][cout], 64B contiguous per thread
        float* vp = &g_votes[((size_t)n * HW + (size_t)(th + py) * WW + (tw + px)) * COUT + c0];
#pragma unroll
        for (int q = 0; q < CCHUNK / 4; ++q) {
            float4 v4 = make_float4(acc[q * 4 + 0], acc[q * 4 + 1],
                                    acc[q * 4 + 2], acc[q * 4 + 3]);
            *(float4*)&vp[q * 4] = v4;
        }
    }
}

// ---------------------------------------------------------------------------
// Routing kernel: CTA = 8 consecutive pixels (same b, same h row), 8 warps,
// warp <-> pixel, lane <-> atom. Votes tile (8 pix x 8 ic x 256) staged once
// in SMEM; 3 routing iterations read only SMEM. Output written coalesced-ish
// via an activation staging buffer.
// ---------------------------------------------------------------------------
__global__ __launch_bounds__(256) void routing_kernel(
    const float* __restrict__ bias,   // [NC][NA]
    float* __restrict__ out)          // [BB][NC][NA][HH][WW]
{
    extern __shared__ float smem[];
    float* sv   = smem;            // [8][ICAPS][COUT]  16384 floats
    float* slog = sv + 8 * ICAPS * COUT;   // [8][ICAPS][NC]  512
    float* srt  = slog + 8 * ICAPS * NC;   // [8][ICAPS][NC]  512
    float* sact = srt + 8 * ICAPS * NC;    // [8][COUT]       2048

    const int tid  = threadIdx.x;
    const int warp = tid >> 5;   // local pixel 0..7
    const int lane = tid & 31;   // atom

    const int cta = blockIdx.x;       // b(8) * h(64) * wgroup(8)
    const int b   = cta >> 9;
    const int h   = (cta >> 3) & 63;
    const int wg  = cta & 7;
    const int pixbase = h * WW + wg * 8;

    // Stage votes: sv[p][ic][cout] <- g_votes[(b*8+ic)][pixbase+p][cout]
    for (int i = tid; i < 8 * ICAPS * COUT; i += 256) {
        int p    = i >> 11;          // /2048
        int ic   = (i >> 8) & 7;
        int cout = i & 255;
        sv[i] = g_votes[(((size_t)(b * ICAPS + ic)) * HW + pixbase + p) * COUT + cout];
    }
    // Zero logits
    for (int i = tid; i < 8 * ICAPS * NC; i += 256) slog[i] = 0.0f;

    // Per-lane bias: bias[nc][lane]
    float bv[NC];
#pragma unroll
    for (int nc = 0; nc < NC; ++nc) bv[nc] = bias[nc * NA + lane];

    __syncthreads();

    const float* svp = &sv[warp * ICAPS * COUT];
    float* slogp = &slog[warp * ICAPS * NC];
    float* srtp  = &srt[warp * ICAPS * NC];

    float p_[NC];
    float a_[NC];

#pragma unroll 1
    for (int it = 0; it < 3; ++it) {
        // Softmax over nc, lanes 0..7 each handle one ic
        if (lane < ICAPS) {
            const int ic = lane;
            float l[NC];
            float mx = -1e30f;
#pragma unroll
            for (int nc = 0; nc < NC; ++nc) {
                l[nc] = slogp[ic * NC + nc];
                mx = fmaxf(mx, l[nc]);
            }
            float s = 0.0f;
#pragma unroll
            for (int nc = 0; nc < NC; ++nc) {
                l[nc] = __expf(l[nc] - mx);
                s += l[nc];
            }
            float inv = 1.0f / s;
#pragma unroll
            for (int nc = 0; nc < NC; ++nc) srtp[ic * NC + nc] = l[nc] * inv;
        }
        __syncwarp();

        // preactivate: p[nc] = bias + sum_ic route[ic][nc] * v[ic][nc][lane]
#pragma unroll
        for (int nc = 0; nc < NC; ++nc) p_[nc] = bv[nc];
#pragma unroll
        for (int ic = 0; ic < ICAPS; ++ic) {
#pragma unroll
            for (int nc = 0; nc < NC; ++nc) {
                p_[nc] += srtp[ic * NC + nc] * svp[ic * COUT + nc * NA + lane];
            }
        }

        // squash: a = p * norm/(1+norm^2), norm over atoms (warp reduce)
#pragma unroll
        for (int nc = 0; nc < NC; ++nc) {
            float s = p_[nc] * p_[nc];
#pragma unroll
            for (int o = 16; o > 0; o >>= 1) s += __shfl_xor_sync(0xFFFFFFFFu, s, o);
            float scale = sqrtf(s) / (1.0f + s);
            a_[nc] = p_[nc] * scale;
        }

        if (it < 2) {
            // distances: d[ic][nc] = sum_atoms v * a ; logits += d
#pragma unroll
            for (int ic = 0; ic < ICAPS; ++ic) {
#pragma unroll
                for (int nc = 0; nc < NC; ++nc) {
                    float d = svp[ic * COUT + nc * NA + lane] * a_[nc];
#pragma unroll
                    for (int o = 16; o > 0; o >>= 1) d += __shfl_xor_sync(0xFFFFFFFFu, d, o);
                    if (lane == 0) slogp[ic * NC + nc] += d;
                }
            }
            __syncwarp();
        }
    }

    // Stage activation, then write out coalesced by (nc,na)
#pragma unroll
    for (int nc = 0; nc < NC; ++nc) sact[warp * COUT + nc * NA + lane] = a_[nc];
    __syncthreads();

    const int cout = tid;  // nc*32+na
    float* op = out + ((size_t)b * COUT + cout) * HW + pixbase;
#pragma unroll
    for (int p = 0; p < 8; ++p) op[p] = sact[p * COUT + cout];
}

// ---------------------------------------------------------------------------
extern "C" void kernel_launch(void* const* d_in, const int* in_sizes, int n_in,
                              void* d_out, int out_size)
{
    const float* x    = (const float*)d_in[0];  // [8,8,32,64,64]
    const float* Wt   = (const float*)d_in[1];  // [256,32,5,5]
    const float* bias = (const float*)d_in[2];  // [1,1,8,32]
    float* out = (float*)d_out;                 // [8,8,32,64,64]

    const int conv_smem = (KVOL * CCHUNK + IA * 400) * (int)sizeof(float);       // 102400 B
    const int rout_smem = (8 * ICAPS * COUT + 2 * 8 * ICAPS * NC + 8 * COUT)
                          * (int)sizeof(float);                                   // 77824 B

    cudaFuncSetAttribute(conv_votes_kernel,
                         cudaFuncAttributeMaxDynamicSharedMemorySize, conv_smem);
    cudaFuncSetAttribute(routing_kernel,
                         cudaFuncAttributeMaxDynamicSharedMemorySize, rout_smem);

    conv_votes_kernel<<<dim3(16, 64), 256, conv_smem>>>(x, Wt);
    routing_kernel<<<BB * HH * (WW / 8), 256, rout_smem>>>(bias, out);
}

// round 7
// speedup vs baseline: 4.9321x; 4.9277x over previous
#include <cuda_runtime.h>
#include <cuda_bf16.h>
#include <stdint.h>
#include <math.h>

// ---------------- scratch ----------------
__device__ __align__(16) float         g_votes[(size_t)64 * 4096 * 256]; // [n][pix][cout]
__device__ __align__(16) __nv_bfloat16 g_xh[(size_t)64 * 4096 * 32];     // [n][h][w][cin] hi
__device__ __align__(16) __nv_bfloat16 g_xl[(size_t)64 * 4096 * 32];     // lo
__device__ __align__(16) __nv_bfloat16 g_wb[25 * 2 * 8192];              // [s][prec][swizzled 256x32]

// ---------------- helpers ----------------
__device__ __forceinline__ void cp16(uint32_t dst, const void* src, int sz) {
    asm volatile("cp.async.cg.shared.global [%0], [%1], 16, %2;"
                 :: "r"(dst), "l"(src), "r"(sz));
}
__device__ __forceinline__ void cp_commit() { asm volatile("cp.async.commit_group;" ::: "memory"); }
template <int N> __device__ __forceinline__ void cp_wait() {
    asm volatile("cp.async.wait_group %0;" :: "n"(N) : "memory");
}
__device__ __forceinline__ void ldsm4(uint32_t* r, uint32_t addr) {
    asm volatile("ldmatrix.sync.aligned.m8n8.x4.shared.b16 {%0,%1,%2,%3}, [%4];"
                 : "=r"(r[0]), "=r"(r[1]), "=r"(r[2]), "=r"(r[3]) : "r"(addr));
}
__device__ __forceinline__ void mma16816(float* c, const uint32_t* a, const uint32_t* b) {
    asm volatile("mma.sync.aligned.m16n8k16.row.col.f32.bf16.bf16.f32 "
                 "{%0,%1,%2,%3}, {%4,%5,%6,%7}, {%8,%9}, {%0,%1,%2,%3};"
                 : "+f"(c[0]), "+f"(c[1]), "+f"(c[2]), "+f"(c[3])
                 : "r"(a[0]), "r"(a[1]), "r"(a[2]), "r"(a[3]), "r"(b[0]), "r"(b[1]));
}
// XOR swizzle for rows of 64B (4x16B chunks), paired into 128B lines:
// conflict-free for ldmatrix (8 rows, fixed chunk) and for cp.async fills.
__device__ __forceinline__ uint32_t swz(int row, int c) {
    return ((row >> 1) << 7) + (((((row & 1) << 2) | c) ^ ((row >> 1) & 7)) << 4);
}
__device__ __forceinline__ float wred(float x) {
#pragma unroll
    for (int o = 16; o; o >>= 1) x += __shfl_xor_sync(0xFFFFFFFFu, x, o);
    return x;
}

// ---------------- prep: x -> [n][h][w][cin] bf16 hi/lo ----------------
__global__ __launch_bounds__(256) void prep_x_kernel(const float* __restrict__ x) {
    __shared__ float sT[32 * 65];
    const int tid = threadIdx.x;
    const int n = blockIdx.x >> 6, h = blockIdx.x & 63;
#pragma unroll
    for (int k = 0; k < 8; ++k) {
        int idx = tid + k * 256;              // 2048 = 32 cin x 64 w
        int cin = idx >> 6, w = idx & 63;
        sT[cin * 65 + w] = x[((size_t)(n * 32 + cin)) * 4096 + h * 64 + w];
    }
    __syncthreads();
#pragma unroll
    for (int k = 0; k < 8; ++k) {
        int idx = tid + k * 256;
        int w = idx >> 5, cin = idx & 31;
        float v = sT[cin * 65 + w];
        __nv_bfloat16 hi = __float2bfloat16(v);
        float lo = v - __bfloat162float(hi);
        size_t o = ((size_t)blockIdx.x * 64 + w) * 32 + cin;
        g_xh[o] = hi;
        g_xl[o] = __float2bfloat16(lo);
    }
}

// ---------------- prep: W -> per-shift swizzled bf16 hi/lo B tiles ----------------
// g_wb[(s*2+prec)*8192 + e], e encodes swizzled [256 cout][32 cin] tile.
__global__ __launch_bounds__(256) void prep_w_kernel(const float* __restrict__ W) {
    const int s = blockIdx.x;                 // shift 0..24
    for (int e = threadIdx.x; e < 16384; e += 256) {
        int prec = e >> 13, rem = e & 8191;
        int q = rem >> 3, i = rem & 7;        // 16B chunk q, element i
        int line = q >> 3, cf = q & 7;
        int t = cf ^ (line & 7);
        int row = line * 2 + (t >> 2);        // cout 0..255
        int c = t & 3;                        // cin chunk
        int cin = c * 8 + i;
        float v = W[row * 800 + cin * 25 + s];
        __nv_bfloat16 hi = __float2bfloat16(v);
        __nv_bfloat16 o = prec ? __float2bfloat16(v - __bfloat162float(hi)) : hi;
        g_wb[(s * 2 + prec) * 8192 + rem] = o;
    }
}

// ---------------- conv: mma.sync bf16 implicit GEMM, 3-product hi/lo ----------------
// CTA = (strip: image n, 2 rows) x (cout half). M=128 pixels, N=128 couts, 25 K=32 stages.
// SMEM per buffer: A hi 8K | A lo 8K | B hi 8K | B lo 8K = 32KB; double buffered = 64KB.
__global__ __launch_bounds__(256) void conv_mma_kernel() {
    extern __shared__ char smem[];
    const uint32_t sb = (uint32_t)__cvta_generic_to_shared(smem);
    const int tid = threadIdx.x, wid = tid >> 5, lane = tid & 31;
    const int bx = blockIdx.x;
    const int nh = bx & 1;
    const int strip = bx >> 1;
    const int n = strip >> 5, h0 = (strip & 31) * 2;

    // ---- per-thread cp.async contexts (2 A-chunks, 2 B-chunks; reused for both precs)
    int amh[2], amw[2], acin[2];
    uint32_t aswz[2], bswz[2];
#pragma unroll
    for (int j = 0; j < 2; ++j) {
        int rem = tid + j * 256;          // 0..511 = 128 rows x 4 chunks
        int row = rem >> 2, c = rem & 3;
        amh[j] = row >> 6; amw[j] = row & 63; acin[j] = c * 8;
        aswz[j] = swz(row, c);
        bswz[j] = swz(row, c);            // B local rows 0..127, same decomposition
    }
    const __nv_bfloat16* xh = g_xh + (size_t)n * 4096 * 32;
    const __nv_bfloat16* xl = g_xl + (size_t)n * 4096 * 32;
    const char* wbase = (const char*)g_wb + nh * 8192;  // byte offset of this cout-half

    auto load_stage = [&](int s, int buf) {
        const int ky = s / 5, kx = s - 5 * ky;
        const uint32_t abase = sb + buf * 32768;
        const uint32_t bbase = abase + 16384;
#pragma unroll
        for (int j = 0; j < 2; ++j) {
            int hh = h0 + amh[j] + ky - 2;
            int ww = amw[j] + kx - 2;
            bool ok = ((unsigned)hh < 64u) && ((unsigned)ww < 64u);
            long eo = ok ? ((long)(hh * 64 + ww) * 32 + acin[j]) : 0;
            int sz = ok ? 16 : 0;
            cp16(abase + aswz[j],        xh + eo, sz);
            cp16(abase + 8192 + aswz[j], xl + eo, sz);
        }
        const char* ws = wbase + s * 32768;   // (s*2+prec)*16384 bytes; prec1 at +16384
#pragma unroll
        for (int j = 0; j < 2; ++j) {
            cp16(bbase + bswz[j],        ws + bswz[j],         16);
            cp16(bbase + 8192 + bswz[j], ws + 16384 + bswz[j], 16);
        }
    };

    // ---- accumulators: warp tile 32(M) x 64(N); grid 4(M) x 2(N)
    const int mrow0 = (wid >> 1) * 32;
    const int ncol0 = (wid & 1) * 64;
    float cacc[2][8][4];
#pragma unroll
    for (int a = 0; a < 2; ++a)
#pragma unroll
        for (int b = 0; b < 8; ++b)
#pragma unroll
            for (int d = 0; d < 4; ++d) cacc[a][b][d] = 0.0f;

    // ldmatrix lane offsets
    const int arow_off = (lane & 7) + ((lane >> 3) & 1) * 8;
    const int ac_off   = lane >> 4;
    const int brow_off = (lane & 7) + ((lane >> 4) << 3);
    const int bc_off   = (lane >> 3) & 1;

    load_stage(0, 0); cp_commit();
    load_stage(1, 1); cp_commit();

#pragma unroll 1
    for (int s = 0; s < 25; ++s) {
        const int buf = s & 1;
        if (s < 23) cp_wait<1>(); else cp_wait<0>();
        __syncthreads();

        const uint32_t abase = sb + buf * 32768;
        const uint32_t bbase = abase + 16384;
#pragma unroll
        for (int ks = 0; ks < 2; ++ks) {
            const int cA = ks * 2 + ac_off;
            const int cB = ks * 2 + bc_off;
            uint32_t ah[2][4], al[2][4];
#pragma unroll
            for (int mt = 0; mt < 2; ++mt) {
                uint32_t o = swz(mrow0 + mt * 16 + arow_off, cA);
                ldsm4(ah[mt], abase + o);
                ldsm4(al[mt], abase + 8192 + o);
            }
#pragma unroll
            for (int nt = 0; nt < 4; ++nt) {
                uint32_t o = swz(ncol0 + nt * 16 + brow_off, cB);
                uint32_t bh[4], bl[4];
                ldsm4(bh, bbase + o);
                ldsm4(bl, bbase + 8192 + o);
#pragma unroll
                for (int mt = 0; mt < 2; ++mt) {
                    mma16816(cacc[mt][2 * nt],     ah[mt], bh);
                    mma16816(cacc[mt][2 * nt + 1], ah[mt], bh + 2);
                    mma16816(cacc[mt][2 * nt],     al[mt], bh);
                    mma16816(cacc[mt][2 * nt + 1], al[mt], bh + 2);
                    mma16816(cacc[mt][2 * nt],     ah[mt], bl);
                    mma16816(cacc[mt][2 * nt + 1], ah[mt], bl + 2);
                }
            }
        }
        __syncthreads();
        if (s + 2 < 25) { load_stage(s + 2, buf); cp_commit(); }
    }

    // ---- epilogue: C frags -> g_votes[n][pix][cout]
    const int g = lane >> 2, cc = (lane & 3) * 2;
#pragma unroll
    for (int mt = 0; mt < 2; ++mt) {
#pragma unroll
        for (int half = 0; half < 2; ++half) {
            int m = mrow0 + mt * 16 + g + half * 8;
            int pix = (h0 + (m >> 6)) * 64 + (m & 63);
            float* vp = g_votes + ((size_t)n * 4096 + pix) * 256 + nh * 128 + ncol0 + cc;
#pragma unroll
            for (int n8 = 0; n8 < 8; ++n8) {
                float2 v = make_float2(cacc[mt][n8][half * 2], cacc[mt][n8][half * 2 + 1]);
                *(float2*)(vp + n8 * 8) = v;
            }
        }
    }
}

// ---------------- routing: register-resident votes ----------------
__global__ __launch_bounds__(256) void routing_kernel(const float* __restrict__ bias,
                                                      float* __restrict__ out) {
    __shared__ float sact[8 * 256];
    const int tid = threadIdx.x, warp = tid >> 5, lane = tid & 31;
    const int b = blockIdx.x >> 9, h = (blockIdx.x >> 3) & 63, wg = blockIdx.x & 7;
    const int pixbase = h * 64 + wg * 8;
    const int pix = pixbase + warp;

    float v[8][8];
#pragma unroll
    for (int ic = 0; ic < 8; ++ic) {
        const float* vp = g_votes + ((size_t)(b * 8 + ic) * 4096 + pix) * 256 + lane;
#pragma unroll
        for (int nc = 0; nc < 8; ++nc) v[ic][nc] = vp[nc * 32];
    }
    float bv[8];
#pragma unroll
    for (int nc = 0; nc < 8; ++nc) bv[nc] = bias[nc * 32 + lane];

    const int my_ic = lane & 7;
    float lg[8];
#pragma unroll
    for (int nc = 0; nc < 8; ++nc) lg[nc] = 0.0f;

    float a[8];
#pragma unroll 1
    for (int it = 0; it < 3; ++it) {
        float mx = lg[0];
#pragma unroll
        for (int nc = 1; nc < 8; ++nc) mx = fmaxf(mx, lg[nc]);
        float r[8], ssum = 0.0f;
#pragma unroll
        for (int nc = 0; nc < 8; ++nc) { r[nc] = __expf(lg[nc] - mx); ssum += r[nc]; }
        float inv = 1.0f / ssum;
#pragma unroll
        for (int nc = 0; nc < 8; ++nc) r[nc] *= inv;

        float p[8];
#pragma unroll
        for (int nc = 0; nc < 8; ++nc) p[nc] = bv[nc];
#pragma unroll
        for (int ic = 0; ic < 8; ++ic) {
#pragma unroll
            for (int nc = 0; nc < 8; ++nc)
                p[nc] += __shfl_sync(0xFFFFFFFFu, r[nc], ic) * v[ic][nc];
        }
#pragma unroll
        for (int nc = 0; nc < 8; ++nc) {
            float s2 = wred(p[nc] * p[nc]);
            a[nc] = p[nc] * (sqrtf(s2) / (1.0f + s2));
        }
        if (it < 2) {
#pragma unroll
            for (int ic = 0; ic < 8; ++ic) {
#pragma unroll
                for (int nc = 0; nc < 8; ++nc) {
                    float d = wred(v[ic][nc] * a[nc]);
                    if (ic == my_ic) lg[nc] += d;
                }
            }
        }
    }
#pragma unroll
    for (int nc = 0; nc < 8; ++nc) sact[warp * 256 + nc * 32 + lane] = a[nc];
    __syncthreads();
    float* op = out + ((size_t)b * 256 + tid) * 4096 + pixbase;
#pragma unroll
    for (int p2 = 0; p2 < 8; ++p2) op[p2] = sact[p2 * 256 + tid];
}

// ---------------------------------------------------------------------------
extern "C" void kernel_launch(void* const* d_in, const int* in_sizes, int n_in,
                              void* d_out, int out_size)
{
    const float* x    = (const float*)d_in[0];  // [8,8,32,64,64]
    const float* Wt   = (const float*)d_in[1];  // [256,32,5,5]
    const float* bias = (const float*)d_in[2];  // [1,1,8,32]
    float* out = (float*)d_out;                 // [8,8,32,64,64]

    const int conv_smem = 65536;
    cudaFuncSetAttribute(conv_mma_kernel,
                         cudaFuncAttributeMaxDynamicSharedMemorySize, conv_smem);

    prep_x_kernel<<<64 * 64, 256>>>(x);
    prep_w_kernel<<<25, 256>>>(Wt);
    conv_mma_kernel<<<4096, 256, conv_smem>>>();
    routing_kernel<<<8 * 64 * 8, 256>>>(bias, out);
}

// round 8
// speedup vs baseline: 5.2512x; 1.0647x over previous
#include <cuda_runtime.h>
#include <cuda_bf16.h>
#include <stdint.h>
#include <math.h>

// ---------------- scratch ----------------
__device__ __align__(16) float         g_votes[(size_t)64 * 4096 * 256]; // [n][pix][cout]
__device__ __align__(16) __nv_bfloat16 g_xh[(size_t)64 * 4096 * 32];     // [n][h][w][cin] hi
__device__ __align__(16) __nv_bfloat16 g_xl[(size_t)64 * 4096 * 32];     // lo
__device__ __align__(16) __nv_bfloat16 g_wb[25 * 2 * 8192];              // [s][prec][swizzled 256x32]

// ---------------- helpers ----------------
__device__ __forceinline__ void cp16(uint32_t dst, const void* src, int sz) {
    asm volatile("cp.async.cg.shared.global [%0], [%1], 16, %2;"
                 :: "r"(dst), "l"(src), "r"(sz));
}
__device__ __forceinline__ void cp_commit() { asm volatile("cp.async.commit_group;" ::: "memory"); }
template <int N> __device__ __forceinline__ void cp_wait() {
    asm volatile("cp.async.wait_group %0;" :: "n"(N) : "memory");
}
__device__ __forceinline__ void ldsm4(uint32_t* r, uint32_t addr) {
    asm volatile("ldmatrix.sync.aligned.m8n8.x4.shared.b16 {%0,%1,%2,%3}, [%4];"
                 : "=r"(r[0]), "=r"(r[1]), "=r"(r[2]), "=r"(r[3]) : "r"(addr));
}
__device__ __forceinline__ void mma16816(float* c, const uint32_t* a, const uint32_t* b) {
    asm volatile("mma.sync.aligned.m16n8k16.row.col.f32.bf16.bf16.f32 "
                 "{%0,%1,%2,%3}, {%4,%5,%6,%7}, {%8,%9}, {%0,%1,%2,%3};"
                 : "+f"(c[0]), "+f"(c[1]), "+f"(c[2]), "+f"(c[3])
                 : "r"(a[0]), "r"(a[1]), "r"(a[2]), "r"(a[3]), "r"(b[0]), "r"(b[1]));
}
// XOR swizzle for rows of 64B (4x16B chunks), paired into 128B lines.
__device__ __forceinline__ uint32_t swz(int row, int c) {
    return ((row >> 1) << 7) + (((((row & 1) << 2) | c) ^ ((row >> 1) & 7)) << 4);
}
__device__ __forceinline__ float wred(float x) {
#pragma unroll
    for (int o = 16; o; o >>= 1) x += __shfl_xor_sync(0xFFFFFFFFu, x, o);
    return x;
}

// ---------------- prep: x -> [n][h][w][cin] bf16 hi/lo ----------------
__global__ __launch_bounds__(256) void prep_x_kernel(const float* __restrict__ x) {
    __shared__ float sT[32 * 65];
    const int tid = threadIdx.x;
    const int n = blockIdx.x >> 6, h = blockIdx.x & 63;
#pragma unroll
    for (int k = 0; k < 8; ++k) {
        int idx = tid + k * 256;              // 2048 = 32 cin x 64 w
        int cin = idx >> 6, w = idx & 63;
        sT[cin * 65 + w] = x[((size_t)(n * 32 + cin)) * 4096 + h * 64 + w];
    }
    __syncthreads();
#pragma unroll
    for (int k = 0; k < 8; ++k) {
        int idx = tid + k * 256;
        int w = idx >> 5, cin = idx & 31;
        float v = sT[cin * 65 + w];
        __nv_bfloat16 hi = __float2bfloat16(v);
        float lo = v - __bfloat162float(hi);
        size_t o = ((size_t)blockIdx.x * 64 + w) * 32 + cin;
        g_xh[o] = hi;
        g_xl[o] = __float2bfloat16(lo);
    }
}

// ---------------- prep: W -> per-shift swizzled bf16 hi/lo B tiles ----------------
__global__ __launch_bounds__(256) void prep_w_kernel(const float* __restrict__ W) {
    const int s = blockIdx.x;                 // shift 0..24
    for (int e = threadIdx.x; e < 16384; e += 256) {
        int prec = e >> 13, rem = e & 8191;
        int q = rem >> 3, i = rem & 7;        // 16B chunk q, element i
        int line = q >> 3, cf = q & 7;
        int t = cf ^ (line & 7);
        int row = line * 2 + (t >> 2);        // cout 0..255
        int c = t & 3;                        // cin chunk
        int cin = c * 8 + i;
        float v = W[row * 800 + cin * 25 + s];
        __nv_bfloat16 hi = __float2bfloat16(v);
        __nv_bfloat16 o = prec ? __float2bfloat16(v - __bfloat162float(hi)) : hi;
        g_wb[(s * 2 + prec) * 8192 + rem] = o;
    }
}

// ---------------- conv: mma.sync bf16 implicit GEMM, 3-product hi/lo ----------------
// CTA = (strip: image n, 2 rows) x (cout half). M=128 pixels, N=128 couts, 25 K=32 stages.
// SMEM per buffer: A hi 8K | A lo 8K | B hi 8K | B lo 8K = 32KB; double buffered = 64KB.
// __launch_bounds__(256, 2): force regs<=128 so 2 CTAs co-reside per SM and
// interleave across the per-stage sync/wait bubbles.
__global__ __launch_bounds__(256, 2) void conv_mma_kernel() {
    extern __shared__ char smem[];
    const uint32_t sb = (uint32_t)__cvta_generic_to_shared(smem);
    const int tid = threadIdx.x, wid = tid >> 5, lane = tid & 31;
    const int bx = blockIdx.x;
    const int nh = bx & 1;
    const int strip = bx >> 1;
    const int n = strip >> 5, h0 = (strip & 31) * 2;

    // per-thread cp.async contexts (2 A-chunks, 2 B-chunks; reused for both precs)
    int amh[2], amw[2], acin[2];
    uint32_t aswz[2], bswz[2];
#pragma unroll
    for (int j = 0; j < 2; ++j) {
        int rem = tid + j * 256;          // 0..511 = 128 rows x 4 chunks
        int row = rem >> 2, c = rem & 3;
        amh[j] = row >> 6; amw[j] = row & 63; acin[j] = c * 8;
        aswz[j] = swz(row, c);
        bswz[j] = swz(row, c);
    }
    const __nv_bfloat16* xh = g_xh + (size_t)n * 4096 * 32;
    const __nv_bfloat16* xl = g_xl + (size_t)n * 4096 * 32;
    const char* wbase = (const char*)g_wb + nh * 8192;

    auto load_stage = [&](int s, int buf) {
        const int ky = s / 5, kx = s - 5 * ky;
        const uint32_t abase = sb + buf * 32768;
        const uint32_t bbase = abase + 16384;
#pragma unroll
        for (int j = 0; j < 2; ++j) {
            int hh = h0 + amh[j] + ky - 2;
            int ww = amw[j] + kx - 2;
            bool ok = ((unsigned)hh < 64u) && ((unsigned)ww < 64u);
            long eo = ok ? ((long)(hh * 64 + ww) * 32 + acin[j]) : 0;
            int sz = ok ? 16 : 0;
            cp16(abase + aswz[j],        xh + eo, sz);
            cp16(abase + 8192 + aswz[j], xl + eo, sz);
        }
        const char* ws = wbase + s * 32768;
#pragma unroll
        for (int j = 0; j < 2; ++j) {
            cp16(bbase + bswz[j],        ws + bswz[j],         16);
            cp16(bbase + 8192 + bswz[j], ws + 16384 + bswz[j], 16);
        }
    };

    // accumulators: warp tile 32(M) x 64(N); grid 4(M) x 2(N)
    const int mrow0 = (wid >> 1) * 32;
    const int ncol0 = (wid & 1) * 64;
    float cacc[2][8][4];
#pragma unroll
    for (int a = 0; a < 2; ++a)
#pragma unroll
        for (int b = 0; b < 8; ++b)
#pragma unroll
            for (int d = 0; d < 4; ++d) cacc[a][b][d] = 0.0f;

    const int arow_off = (lane & 7) + ((lane >> 3) & 1) * 8;
    const int ac_off   = lane >> 4;
    const int brow_off = (lane & 7) + ((lane >> 4) << 3);
    const int bc_off   = (lane >> 3) & 1;

    load_stage(0, 0); cp_commit();
    load_stage(1, 1); cp_commit();

#pragma unroll 1
    for (int s = 0; s < 25; ++s) {
        const int buf = s & 1;
        if (s < 23) cp_wait<1>(); else cp_wait<0>();
        __syncthreads();

        const uint32_t abase = sb + buf * 32768;
        const uint32_t bbase = abase + 16384;
#pragma unroll
        for (int ks = 0; ks < 2; ++ks) {
            const int cA = ks * 2 + ac_off;
            const int cB = ks * 2 + bc_off;
            uint32_t ah[2][4], al[2][4];
#pragma unroll
            for (int mt = 0; mt < 2; ++mt) {
                uint32_t o = swz(mrow0 + mt * 16 + arow_off, cA);
                ldsm4(ah[mt], abase + o);
                ldsm4(al[mt], abase + 8192 + o);
            }
#pragma unroll
            for (int nt = 0; nt < 4; ++nt) {
                uint32_t o = swz(ncol0 + nt * 16 + brow_off, cB);
                uint32_t bh[4], bl[4];
                ldsm4(bh, bbase + o);
                ldsm4(bl, bbase + 8192 + o);
#pragma unroll
                for (int mt = 0; mt < 2; ++mt) {
                    mma16816(cacc[mt][2 * nt],     ah[mt], bh);
                    mma16816(cacc[mt][2 * nt + 1], ah[mt], bh + 2);
                    mma16816(cacc[mt][2 * nt],     al[mt], bh);
                    mma16816(cacc[mt][2 * nt + 1], al[mt], bh + 2);
                    mma16816(cacc[mt][2 * nt],     ah[mt], bl);
                    mma16816(cacc[mt][2 * nt + 1], ah[mt], bl + 2);
                }
            }
        }
        __syncthreads();
        if (s + 2 < 25) { load_stage(s + 2, buf); cp_commit(); }
    }

    // epilogue: C frags -> g_votes[n][pix][cout]
    const int g = lane >> 2, cc = (lane & 3) * 2;
#pragma unroll
    for (int mt = 0; mt < 2; ++mt) {
#pragma unroll
        for (int half = 0; half < 2; ++half) {
            int m = mrow0 + mt * 16 + g + half * 8;
            int pix = (h0 + (m >> 6)) * 64 + (m & 63);
            float* vp = g_votes + ((size_t)n * 4096 + pix) * 256 + nh * 128 + ncol0 + cc;
#pragma unroll
            for (int n8 = 0; n8 < 8; ++n8) {
                float2 v = make_float2(cacc[mt][n8][half * 2], cacc[mt][n8][half * 2 + 1]);
                *(float2*)(vp + n8 * 8) = v;
            }
        }
    }
}

// ---------------- routing: register votes + butterfly multi-reduce distances ----
__global__ __launch_bounds__(256) void routing_kernel(const float* __restrict__ bias,
                                                      float* __restrict__ out) {
    __shared__ float sact[8 * 256];
    const int tid = threadIdx.x, warp = tid >> 5, lane = tid & 31;
    const int b = blockIdx.x >> 9, h = (blockIdx.x >> 3) & 63, wg = blockIdx.x & 7;
    const int pixbase = h * 64 + wg * 8;
    const int pix = pixbase + warp;

    float v[8][8];
#pragma unroll
    for (int ic = 0; ic < 8; ++ic) {
        const float* vp = g_votes + ((size_t)(b * 8 + ic) * 4096 + pix) * 256 + lane;
#pragma unroll
        for (int nc = 0; nc < 8; ++nc) v[ic][nc] = vp[nc * 32];
    }
    float bv[8];
#pragma unroll
    for (int nc = 0; nc < 8; ++nc) bv[nc] = bias[nc * 32 + lane];

    const int my_ic = lane & 7;   // logits for ic=lane&7 (duplicated x4)
    float lg[8];
#pragma unroll
    for (int nc = 0; nc < 8; ++nc) lg[nc] = 0.0f;

    float a[8];
#pragma unroll 1
    for (int it = 0; it < 3; ++it) {
        // softmax over nc of this lane's ic
        float mx = lg[0];
#pragma unroll
        for (int nc = 1; nc < 8; ++nc) mx = fmaxf(mx, lg[nc]);
        float r[8], ssum = 0.0f;
#pragma unroll
        for (int nc = 0; nc < 8; ++nc) { r[nc] = __expf(lg[nc] - mx); ssum += r[nc]; }
        float inv = 1.0f / ssum;
#pragma unroll
        for (int nc = 0; nc < 8; ++nc) r[nc] *= inv;

        // preactivate: p[nc] = bias + sum_ic route[ic][nc] * v[ic][nc]
        float p[8];
#pragma unroll
        for (int nc = 0; nc < 8; ++nc) p[nc] = bv[nc];
#pragma unroll
        for (int ic = 0; ic < 8; ++ic) {
#pragma unroll
            for (int nc = 0; nc < 8; ++nc)
                p[nc] += __shfl_sync(0xFFFFFFFFu, r[nc], ic) * v[ic][nc];
        }
        // squash
#pragma unroll
        for (int nc = 0; nc < 8; ++nc) {
            float s2 = wred(p[nc] * p[nc]);
            a[nc] = p[nc] * (sqrtf(s2) / (1.0f + s2));
        }

        if (it < 2) {
            // distances: 64 sums over 32 lanes via butterfly multi-reduce.
            // Two batches of 32 vars (q = icq*8 + nc); after the fold, lane l
            // holds the full sum of var l.
            float d0, d1;
#pragma unroll
            for (int batch = 0; batch < 2; ++batch) {
                float z[16];
#pragma unroll
                for (int j = 0; j < 16; ++j) {
                    int nc = j & 7, icl = j >> 3;
                    float pA = v[batch * 4 + icl][nc]     * a[nc];  // var j
                    float pB = v[batch * 4 + 2 + icl][nc] * a[nc];  // var j+16
                    float send = (lane & 16) ? pA : pB;
                    float recv = __shfl_xor_sync(0xFFFFFFFFu, send, 16);
                    z[j] = ((lane & 16) ? pB : pA) + recv;
                }
#pragma unroll
                for (int o = 8; o; o >>= 1) {
#pragma unroll
                    for (int j = 0; j < o; ++j) {
                        float send = (lane & o) ? z[j] : z[j + o];
                        float recv = __shfl_xor_sync(0xFFFFFFFFu, send, o);
                        z[j] = ((lane & o) ? z[j + o] : z[j]) + recv;
                    }
                }
                if (batch == 0) d0 = z[0]; else d1 = z[0];
            }
            // redistribute: lg[nc] += d(my_ic, nc); source lane = ((my_ic&3)<<3)|nc
#pragma unroll
            for (int nc = 0; nc < 8; ++nc) {
                int src = ((my_ic & 3) << 3) | nc;
                float t0 = __shfl_sync(0xFFFFFFFFu, d0, src);
                float t1 = __shfl_sync(0xFFFFFFFFu, d1, src);
                lg[nc] += (my_ic < 4) ? t0 : t1;
            }
        }
    }
#pragma unroll
    for (int nc = 0; nc < 8; ++nc) sact[warp * 256 + nc * 32 + lane] = a[nc];
    __syncthreads();
    float* op = out + ((size_t)b * 256 + tid) * 4096 + pixbase;
#pragma unroll
    for (int p2 = 0; p2 < 8; ++p2) op[p2] = sact[p2 * 256 + tid];
}

// ---------------------------------------------------------------------------
extern "C" void kernel_launch(void* const* d_in, const int* in_sizes, int n_in,
                              void* d_out, int out_size)
{
    const float* x    = (const float*)d_in[0];  // [8,8,32,64,64]
    const float* Wt   = (const float*)d_in[1];  // [256,32,5,5]
    const float* bias = (const float*)d_in[2];  // [1,1,8,32]
    float* out = (float*)d_out;                 // [8,8,32,64,64]

    const int conv_smem = 65536;
    cudaFuncSetAttribute(conv_mma_kernel,
                         cudaFuncAttributeMaxDynamicSharedMemorySize, conv_smem);

    prep_x_kernel<<<64 * 64, 256>>>(x);
    prep_w_kernel<<<25, 256>>>(Wt);
    conv_mma_kernel<<<4096, 256, conv_smem>>>();
    routing_kernel<<<8 * 64 * 8, 256>>>(bias, out);
}